// round 16
// baseline (speedup 1.0000x reference)
#include <cuda_runtime.h>
#include <cuda_bf16.h>
#include <math.h>

// ---------------------------------------------------------------------------
// Decoder layer, round 16 (= R15 + MoE m-tail MMA guard + fused prep kernel):
//  - attention-path GEMMs (QKV, WO): 3xtf32 2-stage, LDSM A
//  - flash attention: R13 structure, LDSM Q
//  - MoE expert GEMMs: 2-plane bf16 split, LDSM A, per-mt tail guard
// Scratch accessed ONLY as device symbols inside kernels (ATS trap).
// ---------------------------------------------------------------------------

#define S 1024
#define H 2048
#define NH 32
#define NKV 8
#define D 64
#define E 8
#define TOPK 2
#define F 4096
#define EPS 1e-5f
#define MULT 0.125f
#define CAP 30.0f

// ------------------------------ scratch (device globals) --------------------
__device__ float g_xnH[S * H];
__device__ float g_xnL[S * H];
__device__ float g_xnorm[S * H];
__device__ __nv_bfloat16 g_xnB0[S * H];
__device__ __nv_bfloat16 g_xnB1[S * H];
__device__ float g_attnH[S * H];
__device__ float g_attnL[S * H];
__device__ float g_q[S * NH * D];
__device__ float g_k[S * NKV * D];
__device__ float g_v[S * NKV * D];
__device__ float g_qH[S * NH * D];
__device__ float g_qL[S * NH * D];
__device__ float g_kH[S * NKV * D];
__device__ float g_kL[S * NKV * D];
__device__ float g_vH[S * NKV * D];
__device__ float g_vL[S * NKV * D];
__device__ float g_attnproj[S * H];
__device__ float g_hidden[S * H];
__device__ float g_h1[S * TOPK * F];
__device__ __nv_bfloat16 g_h1B0[S * TOPK * F];
__device__ __nv_bfloat16 g_h1B1[S * TOPK * F];
__device__ float g_gout[S * TOPK * H];
__device__ int   g_topi[S * TOPK];
__device__ float g_topw[S * TOPK];
__device__ int   g_offs[E + 1];
__device__ int   g_perm_token[S * TOPK];
__device__ int   g_tok2row[S * TOPK];

// ------------------------------ numeric helpers -----------------------------
__device__ __forceinline__ float f2tf32f(float x) {
    unsigned r;
    asm("cvt.rna.tf32.f32 %0, %1;" : "=r"(r) : "f"(x));
    return __uint_as_float(r);
}
__device__ __forceinline__ void tf32splitf(float x, float& hi, float& lo) {
    hi = f2tf32f(x);
    lo = f2tf32f(x - hi);
}
__device__ __forceinline__ void mma_tf32(float c[4], const unsigned a[4],
                                         const unsigned b[2]) {
    asm volatile(
        "mma.sync.aligned.m16n8k8.row.col.f32.tf32.tf32.f32 "
        "{%0,%1,%2,%3}, {%4,%5,%6,%7}, {%8,%9}, {%0,%1,%2,%3};"
        : "+f"(c[0]), "+f"(c[1]), "+f"(c[2]), "+f"(c[3])
        : "r"(a[0]), "r"(a[1]), "r"(a[2]), "r"(a[3]), "r"(b[0]), "r"(b[1]));
}
__device__ __forceinline__ void mma_bf16(float c[4], const unsigned a[4],
                                         const unsigned b[2]) {
    asm volatile(
        "mma.sync.aligned.m16n8k16.row.col.f32.bf16.bf16.f32 "
        "{%0,%1,%2,%3}, {%4,%5,%6,%7}, {%8,%9}, {%0,%1,%2,%3};"
        : "+f"(c[0]), "+f"(c[1]), "+f"(c[2]), "+f"(c[3])
        : "r"(a[0]), "r"(a[1]), "r"(a[2]), "r"(a[3]), "r"(b[0]), "r"(b[1]));
}
__device__ __forceinline__ void ldsm4(unsigned r[4], unsigned saddr) {
    asm volatile(
        "ldmatrix.sync.aligned.m8n8.x4.shared.b16 {%0,%1,%2,%3}, [%4];"
        : "=r"(r[0]), "=r"(r[1]), "=r"(r[2]), "=r"(r[3]) : "r"(saddr));
}
__device__ __forceinline__ unsigned packbf(float x0, float x1) {
    unsigned d;
    asm("cvt.rn.bf16x2.f32 %0, %1, %2;" : "=r"(d) : "f"(x1), "f"(x0));
    return d;
}
__device__ __forceinline__ void bfsplit2(float x0, float x1,
                                         unsigned& p0, unsigned& p1) {
    unsigned h = packbf(x0, x1);
    float r0 = x0 - __uint_as_float(h << 16);
    float r1 = x1 - __uint_as_float(h & 0xffff0000u);
    p0 = h;
    p1 = packbf(r0, r1);
}
__device__ __forceinline__ void cpa16(unsigned dst, const void* src, bool valid) {
    int sz = valid ? 16 : 0;
    asm volatile("cp.async.ca.shared.global [%0], [%1], 16, %2;\n"
                 :: "r"(dst), "l"(src), "r"(sz));
}
__device__ __forceinline__ float tanh_fast(float x) {
    float z = __expf(-2.f * fabsf(x));
    float th = __fdividef(1.f - z, 1.f + z);
    return copysignf(th, x);
}

// ======================= tf32 GEMM (attention path) =========================
#define STG 7232
#define SMEM_TF (2 * STG * 4)

struct Ctx {
    const float *AH, *AL;
    const float *B;
    float* C;
    int N, K;
    int nBase;
    int mBase, rend;
};

__device__ __forceinline__ void stage_tf(const Ctx& g, float* sm, int sbuf,
                                         int k0, int tid) {
    unsigned base = (unsigned)__cvta_generic_to_shared(sm + sbuf * STG);
#pragma unroll
    for (int i = 0; i < 2; ++i) {
        int idx = tid + i * 256;
        int row = idx >> 2, c4 = (idx & 3) * 4;
        int grow = g.mBase + row;
        bool valid = grow < g.rend;
        size_t off = (size_t)(valid ? grow : 0) * g.K + k0 + c4;
        unsigned d = base + (unsigned)(row * 20 + c4) * 4;
        cpa16(d, g.AH + off, valid);
        cpa16(d + 2560 * 4, g.AL + off, valid);
    }
#pragma unroll
    for (int i = 0; i < 2; ++i) {
        int idx = tid + i * 256;
        int row = idx >> 5, c4 = (idx & 31) * 4;
        size_t off = (size_t)(k0 + row) * g.N + g.nBase + c4;
        unsigned d = base + (unsigned)(5120 + row * 132 + c4) * 4;
        cpa16(d, g.B + off, true);
    }
    asm volatile("cp.async.commit_group;" ::: "memory");
}

__device__ __forceinline__ void gemm_tf(const Ctx& g) {
    extern __shared__ float sm[];
    int tid = threadIdx.x;
    int lane = tid & 31, warp = tid >> 5;
    int wr = warp & 1, wc = warp >> 1;
    int mW = wr * 64, nW = wc * 32;
    int gid = lane >> 2, tig = lane & 3;
    int rowsel = ((lane >> 3) & 1) * 8 + (lane & 7);
    int ksel = (lane >> 4) * 4;

    float acc[4][4][4];
#pragma unroll
    for (int mt = 0; mt < 4; ++mt)
#pragma unroll
        for (int nt = 0; nt < 4; ++nt)
#pragma unroll
            for (int r = 0; r < 4; ++r) acc[mt][nt][r] = 0.f;

    int niters = g.K / 16;
    stage_tf(g, sm, 0, 0, tid);

    for (int it = 0; it < niters; ++it) {
        int cur = it & 1;
        if (it + 1 < niters) {
            stage_tf(g, sm, cur ^ 1, (it + 1) * 16, tid);
            asm volatile("cp.async.wait_group 1;" ::: "memory");
        } else {
            asm volatile("cp.async.wait_group 0;" ::: "memory");
        }
        __syncthreads();

        const float* AHs = sm + cur * STG;
        const float* Bs = AHs + 5120;
        unsigned aBase = (unsigned)__cvta_generic_to_shared(AHs);
#pragma unroll
        for (int kk = 0; kk < 16; kk += 8) {
            unsigned bH[4][2], bL[4][2];
#pragma unroll
            for (int nt = 0; nt < 4; ++nt) {
                int c0 = (kk + tig) * 132 + nW + nt * 8 + gid;
                int c1 = c0 + 528;
                float h0, l0, h1, l1;
                tf32splitf(Bs[c0], h0, l0);
                tf32splitf(Bs[c1], h1, l1);
                bH[nt][0] = __float_as_uint(h0);
                bL[nt][0] = __float_as_uint(l0);
                bH[nt][1] = __float_as_uint(h1);
                bL[nt][1] = __float_as_uint(l1);
            }
#pragma unroll
            for (int mt = 0; mt < 4; ++mt) {
                unsigned off =
                    (unsigned)(((mW + mt * 16 + rowsel) * 20 + kk + ksel) * 4);
                unsigned aH[4], aL[4];
                ldsm4(aH, aBase + off);
                ldsm4(aL, aBase + 2560 * 4 + off);
#pragma unroll
                for (int nt = 0; nt < 4; ++nt) {
                    mma_tf32(acc[mt][nt], aH, bL[nt]);
                    mma_tf32(acc[mt][nt], aL, bH[nt]);
                    mma_tf32(acc[mt][nt], aH, bH[nt]);
                }
            }
        }
        __syncthreads();
    }

#pragma unroll
    for (int mt = 0; mt < 4; ++mt) {
#pragma unroll
        for (int half = 0; half < 2; ++half) {
            int r0 = g.mBase + mW + mt * 16 + gid + half * 8;
            if (r0 >= g.rend) continue;
#pragma unroll
            for (int nt = 0; nt < 4; ++nt) {
                int col = g.nBase + nW + nt * 8 + tig * 2;
                *(float2*)&g.C[(size_t)r0 * g.N + col] =
                    make_float2(acc[mt][nt][half * 2], acc[mt][nt][half * 2 + 1]);
            }
        }
    }
}

__global__ void __launch_bounds__(256, 2) tgemm_qkv_kernel(
    const float* __restrict__ wq, const float* __restrict__ wk,
    const float* __restrict__ wv) {
    int bx = blockIdx.x;
    Ctx g;
    g.AH = g_xnH; g.AL = g_xnL;
    g.K = H;
    g.mBase = blockIdx.y * 128;
    g.rend = S;
    if (bx < 16) {
        g.B = wq; g.C = g_q; g.N = 2048; g.nBase = bx * 128;
    } else if (bx < 20) {
        g.B = wk; g.C = g_k; g.N = 512; g.nBase = (bx - 16) * 128;
    } else {
        g.B = wv; g.C = g_v; g.N = 512; g.nBase = (bx - 20) * 128;
    }
    gemm_tf(g);
}

__global__ void __launch_bounds__(256, 2) tgemm_wo_kernel(
    const float* __restrict__ wo) {
    Ctx g;
    g.AH = g_attnH; g.AL = g_attnL;
    g.B = wo;
    g.C = g_attnproj;
    g.N = H; g.K = H;
    g.nBase = blockIdx.x * 128;
    g.mBase = blockIdx.y * 128;
    g.rend = S;
    gemm_tf(g);
}

// ======================= bf16x2-split GEMM (MoE path) =======================
#define BSTG 37376
#define SMEM_BF (2 * BSTG)

__global__ void __launch_bounds__(256, 2) bgemm_group_kernel(
    const float* __restrict__ W, int which) {
    int e = blockIdx.z;
    int rbeg = g_offs[e], rend = g_offs[e + 1];
    int mBase = rbeg + blockIdx.y * 128;
    if (mBase >= rend) return;

    const __nv_bfloat16 *A0, *A1;
    const float* B;
    float* C;
    int N, K, useGather, epi;
    if (which == 2) {
        A0 = g_h1B0; A1 = g_h1B1; useGather = 0; epi = 0;
        B = W + (size_t)e * F * H; C = g_gout; N = H; K = F;
    } else {
        A0 = g_xnB0; A1 = g_xnB1; useGather = 1; epi = which;
        B = W + (size_t)e * H * F; C = g_h1; N = F; K = H;
    }
    int nBase = blockIdx.x * 128;

    extern __shared__ char smc[];
    int tid = threadIdx.x;
    int lane = tid & 31, warp = tid >> 5;
    int wr = warp & 1, wc = warp >> 1;
    int mW = wr * 64, nW = wc * 32;
    int gid = lane >> 2, tig = lane & 3;
    int rowsel = ((lane >> 3) & 1) * 8 + (lane & 7);
    int ksel16 = (lane >> 4) * 16;
    // tail guards: skip MMA work for warp-tiles entirely past rend
    bool wActive = (mBase + mW) < rend;
    bool mtAct[4];
#pragma unroll
    for (int mt = 0; mt < 4; ++mt)
        mtAct[mt] = (mBase + mW + mt * 16) < rend;

    float acc[4][4][4];
#pragma unroll
    for (int mt = 0; mt < 4; ++mt)
#pragma unroll
        for (int nt = 0; nt < 4; ++nt)
#pragma unroll
            for (int r = 0; r < 4; ++r) acc[mt][nt][r] = 0.f;

    auto stage = [&](int sbuf, int k0) {
        unsigned base = (unsigned)__cvta_generic_to_shared(smc + sbuf * BSTG);
#pragma unroll
        for (int i = 0; i < 4; ++i) {
            int idx = tid + i * 256;
            int plane = idx >> 9;
            int rem = idx & 511;
            int row = rem >> 2, ch = rem & 3;
            int grow = mBase + row;
            bool valid = grow < rend;
            int arow = valid ? (useGather ? g_perm_token[grow] : grow) : 0;
            const __nv_bfloat16* src = (plane ? A1 : A0) + (size_t)arow * K + k0 + ch * 8;
            unsigned d = base + plane * 10240 + row * 80 + ch * 16;
            cpa16(d, src, valid);
        }
#pragma unroll
        for (int i = 0; i < 4; ++i) {
            int idx = tid + i * 256;
            int row = idx >> 5, ch = idx & 31;
            const float* src = B + (size_t)(k0 + row) * N + nBase + ch * 4;
            unsigned d = base + 20480 + row * 528 + ch * 16;
            cpa16(d, src, true);
        }
        asm volatile("cp.async.commit_group;" ::: "memory");
    };

    int niters = K / 32;
    stage(0, 0);
    for (int it = 0; it < niters; ++it) {
        int cur = it & 1;
        if (it + 1 < niters) {
            stage(cur ^ 1, (it + 1) * 32);
            asm volatile("cp.async.wait_group 1;" ::: "memory");
        } else {
            asm volatile("cp.async.wait_group 0;" ::: "memory");
        }
        __syncthreads();

        if (wActive) {
            const char* sb = smc + cur * BSTG;
            const float* Bs = (const float*)(sb + 20480);
            unsigned aBase = (unsigned)__cvta_generic_to_shared(sb);
#pragma unroll
            for (int s = 0; s < 2; ++s) {
                unsigned bH[4][2], bL[4][2];
#pragma unroll
                for (int nt = 0; nt < 4; ++nt) {
                    int c = nW + nt * 8 + gid;
                    int rb = (s * 16 + 2 * tig) * 132 + c;
                    bfsplit2(Bs[rb], Bs[rb + 132], bH[nt][0], bL[nt][0]);
                    bfsplit2(Bs[rb + 8 * 132], Bs[rb + 9 * 132], bH[nt][1], bL[nt][1]);
                }
#pragma unroll
                for (int mt = 0; mt < 4; ++mt) {
                    if (!mtAct[mt]) continue;
                    unsigned off =
                        (unsigned)((mW + mt * 16 + rowsel) * 80 + s * 32 + ksel16);
                    unsigned aH[4], aL[4];
                    ldsm4(aH, aBase + off);
                    ldsm4(aL, aBase + 10240 + off);
#pragma unroll
                    for (int nt = 0; nt < 4; ++nt) {
                        mma_bf16(acc[mt][nt], aH, bL[nt]);
                        mma_bf16(acc[mt][nt], aL, bH[nt]);
                        mma_bf16(acc[mt][nt], aH, bH[nt]);
                    }
                }
            }
        }
        __syncthreads();
    }

#pragma unroll
    for (int mt = 0; mt < 4; ++mt) {
#pragma unroll
        for (int half = 0; half < 2; ++half) {
            int r0 = mBase + mW + mt * 16 + gid + half * 8;
            if (r0 >= rend) continue;
#pragma unroll
            for (int nt = 0; nt < 4; ++nt) {
                int col = nBase + nW + nt * 8 + tig * 2;
                float v0 = acc[mt][nt][half * 2 + 0];
                float v1 = acc[mt][nt][half * 2 + 1];
                size_t idx = (size_t)r0 * N + col;
                if (epi == 0) {
                    *(float2*)&C[idx] = make_float2(v0, v1);
                } else {
                    float a0 = g_h1[idx], a1 = g_h1[idx + 1];
                    float ge0 = 0.5f * a0 * (1.f + erff(a0 * 0.7071067811865475f));
                    float ge1 = 0.5f * a1 * (1.f + erff(a1 * 0.7071067811865475f));
                    unsigned p0, p1;
                    bfsplit2(ge0 * v0, ge1 * v1, p0, p1);
                    ((unsigned*)g_h1B0)[idx >> 1] = p0;
                    ((unsigned*)g_h1B1)[idx >> 1] = p1;
                }
            }
        }
    }
}

// ======================= tensor-core flash attention ========================
#define FSM_BYTES 212992

__global__ void __launch_bounds__(256, 1) flashmma_kernel() {
    extern __shared__ float sm[];
    float* QH = sm;
    float* QL = sm + 8704;

    int qt = 7 - (int)blockIdx.x;
    int h = blockIdx.y;
    int kv = h >> 2;
    int tid = threadIdx.x;
    int lane = tid & 31, warp = tid >> 5;
    int gid = lane >> 2, tig = lane & 3;
    int qr0 = qt * 128;
    int srcA = (lane & ~3) | (tig >> 1);
    int srcB = srcA + 2;
    bool odd = (tig & 1);
    int rowsel = ((lane >> 3) & 1) * 8 + (lane & 7);
    int ksel = (lane >> 4) * 4;
    unsigned qBase = (unsigned)__cvta_generic_to_shared(QH);

    for (int i = tid; i < 128 * 64; i += 256) {
        int r = i >> 6, d = i & 63;
        size_t gi = (size_t)(qr0 + r) * (NH * D) + h * 64 + d;
        QH[r * 68 + d] = g_qH[gi];
        QL[r * 68 + d] = g_qL[gi];
    }

    auto stageKV = [&](int buf, int k0g) {
        float* bb = sm + 17408 + buf * 17920;
        unsigned base = (unsigned)__cvta_generic_to_shared(bb);
#pragma unroll
        for (int i = 0; i < 16; ++i) {
            int idx = tid + i * 256;
            int plane = idx >> 10;
            int rem = idx & 1023;
            int row = rem >> 4, ch = rem & 15;
            const float* srcp;
            unsigned dst;
            size_t so = (size_t)(k0g + row) * (NKV * D) + kv * 64 + ch * 4;
            if (plane == 0) { srcp = g_kH + so; dst = base + (row * 68 + ch * 4) * 4; }
            else if (plane == 1) { srcp = g_kL + so; dst = base + (4352 + row * 68 + ch * 4) * 4; }
            else if (plane == 2) { srcp = g_vH + so; dst = base + (8704 + row * 72 + ch * 4) * 4; }
            else { srcp = g_vL + so; dst = base + (13312 + row * 72 + ch * 4) * 4; }
            cpa16(dst, srcp, true);
        }
        asm volatile("cp.async.commit_group;" ::: "memory");
    };

    float mrow[2] = {-1e30f, -1e30f};
    float lrow[2] = {0.f, 0.f};
    float oacc[8][4];
#pragma unroll
    for (int nt = 0; nt < 8; ++nt)
#pragma unroll
        for (int c = 0; c < 4; ++c) oacc[nt][c] = 0.f;

    int nkt = 2 * qt + 2;
    stageKV(0, 0);
    for (int kt = 0; kt < nkt; ++kt) {
        int k0g = kt * 64;
        bool domask = (kt >= 2 * qt);
        __syncthreads();
        if (kt + 1 < nkt) {
            stageKV((kt + 1) & 1, (kt + 1) * 64);
            asm volatile("cp.async.wait_group 1;" ::: "memory");
        } else {
            asm volatile("cp.async.wait_group 0;" ::: "memory");
        }
        __syncthreads();

        const float* bb = sm + 17408 + (kt & 1) * 17920;
        const float* KsH = bb;
        const float* KsL = bb + 4352;
        const float* VsH = bb + 8704;
        const float* VsL = bb + 13312;

        float sacc[8][4];
#pragma unroll
        for (int nt = 0; nt < 8; ++nt)
#pragma unroll
            for (int c = 0; c < 4; ++c) sacc[nt][c] = 0.f;
#pragma unroll
        for (int kk = 0; kk < 64; kk += 8) {
            unsigned off =
                (unsigned)(((warp * 16 + rowsel) * 68 + kk + ksel) * 4);
            unsigned aH[4], aL[4];
            ldsm4(aH, qBase + off);
            ldsm4(aL, qBase + 8704 * 4 + off);
#pragma unroll
            for (int nt = 0; nt < 8; ++nt) {
                int kb = (nt * 8 + gid) * 68 + kk + tig;
                unsigned bH[2], bL[2];
                bH[0] = __float_as_uint(KsH[kb]);
                bH[1] = __float_as_uint(KsH[kb + 4]);
                bL[0] = __float_as_uint(KsL[kb]);
                bL[1] = __float_as_uint(KsL[kb + 4]);
                mma_tf32(sacc[nt], aH, bL);
                mma_tf32(sacc[nt], aL, bH);
                mma_tf32(sacc[nt], aH, bH);
            }
        }

#pragma unroll
        for (int nt = 0; nt < 8; ++nt)
#pragma unroll
            for (int c = 0; c < 4; ++c) {
                float v = CAP * tanh_fast(sacc[nt][c] * (MULT / CAP));
                if (domask) {
                    int row = qr0 + warp * 16 + gid + (c >> 1) * 8;
                    int key = k0g + nt * 8 + tig * 2 + (c & 1);
                    if (key > row) v = -1e30f;
                }
                sacc[nt][c] = v;
            }

#pragma unroll
        for (int half = 0; half < 2; ++half) {
            float rm = -1e30f;
#pragma unroll
            for (int nt = 0; nt < 8; ++nt)
                rm = fmaxf(rm, fmaxf(sacc[nt][half * 2], sacc[nt][half * 2 + 1]));
            rm = fmaxf(rm, __shfl_xor_sync(0xffffffffu, rm, 1));
            rm = fmaxf(rm, __shfl_xor_sync(0xffffffffu, rm, 2));
            float mn = fmaxf(mrow[half], rm);
            float scl = __expf(mrow[half] - mn);
            float rs = 0.f;
#pragma unroll
            for (int nt = 0; nt < 8; ++nt) {
                float p0 = __expf(sacc[nt][half * 2] - mn);
                float p1 = __expf(sacc[nt][half * 2 + 1] - mn);
                sacc[nt][half * 2] = p0;
                sacc[nt][half * 2 + 1] = p1;
                rs += p0 + p1;
            }
            rs += __shfl_xor_sync(0xffffffffu, rs, 1);
            rs += __shfl_xor_sync(0xffffffffu, rs, 2);
            lrow[half] = lrow[half] * scl + rs;
            mrow[half] = mn;
#pragma unroll
            for (int nt = 0; nt < 8; ++nt) {
                oacc[nt][half * 2] *= scl;
                oacc[nt][half * 2 + 1] *= scl;
            }
        }

#pragma unroll
        for (int kk = 0; kk < 64; kk += 8) {
            int ntp = kk >> 3;
            float v00 = sacc[ntp][0], v01 = sacc[ntp][1];
            float v10 = sacc[ntp][2], v11 = sacc[ntp][3];
            float s00a = __shfl_sync(0xffffffffu, v00, srcA);
            float s01a = __shfl_sync(0xffffffffu, v01, srcA);
            float s10a = __shfl_sync(0xffffffffu, v10, srcA);
            float s11a = __shfl_sync(0xffffffffu, v11, srcA);
            float s00b = __shfl_sync(0xffffffffu, v00, srcB);
            float s01b = __shfl_sync(0xffffffffu, v01, srcB);
            float s10b = __shfl_sync(0xffffffffu, v10, srcB);
            float s11b = __shfl_sync(0xffffffffu, v11, srcB);
            float a0 = odd ? s01a : s00a;
            float a1 = odd ? s11a : s10a;
            float a2 = odd ? s01b : s00b;
            float a3 = odd ? s11b : s10b;
            unsigned aH[4], aL[4];
            float hi, lo;
            tf32splitf(a0, hi, lo); aH[0] = __float_as_uint(hi); aL[0] = __float_as_uint(lo);
            tf32splitf(a1, hi, lo); aH[1] = __float_as_uint(hi); aL[1] = __float_as_uint(lo);
            tf32splitf(a2, hi, lo); aH[2] = __float_as_uint(hi); aL[2] = __float_as_uint(lo);
            tf32splitf(a3, hi, lo); aH[3] = __float_as_uint(hi); aL[3] = __float_as_uint(lo);
#pragma unroll
            for (int nt = 0; nt < 8; ++nt) {
                int vb = (kk + tig) * 72 + nt * 8 + gid;
                int vb4 = vb + 4 * 72;
                unsigned bH[2], bL[2];
                bH[0] = __float_as_uint(VsH[vb]);
                bH[1] = __float_as_uint(VsH[vb4]);
                bL[0] = __float_as_uint(VsL[vb]);
                bL[1] = __float_as_uint(VsL[vb4]);
                mma_tf32(oacc[nt], aH, bL);
                mma_tf32(oacc[nt], aL, bH);
                mma_tf32(oacc[nt], aH, bH);
            }
        }
    }

#pragma unroll
    for (int half = 0; half < 2; ++half) {
        float invl = 1.f / lrow[half];
        int row = qr0 + warp * 16 + gid + half * 8;
#pragma unroll
        for (int nt = 0; nt < 8; ++nt) {
            float o0 = oacc[nt][half * 2] * invl;
            float o1 = oacc[nt][half * 2 + 1] * invl;
            float h0, l0, h1, l1;
            tf32splitf(o0, h0, l0);
            tf32splitf(o1, h1, l1);
            size_t idx = (size_t)row * H + h * 64 + nt * 8 + tig * 2;
            *(float2*)&g_attnH[idx] = make_float2(h0, h1);
            *(float2*)&g_attnL[idx] = make_float2(l0, l1);
        }
    }
}

// ------------------------------ rmsnorm (attention input) -------------------
__global__ void rmsnorm_attn_kernel(const float* __restrict__ x,
                                    const float* __restrict__ w) {
    int row = blockIdx.x;
    int tid = threadIdx.x;
    const float* xr = x + (size_t)row * H;
    float ss = 0.f;
    float loc[8];
#pragma unroll
    for (int t = 0; t < 8; ++t) {
        float v = xr[tid + t * 256];
        loc[t] = v;
        ss += v * v;
    }
    __shared__ float red[256];
    red[tid] = ss;
    __syncthreads();
    for (int s2 = 128; s2 > 0; s2 >>= 1) {
        if (tid < s2) red[tid] += red[tid + s2];
        __syncthreads();
    }
    float inv = rsqrtf(red[0] / (float)H + EPS);
#pragma unroll
    for (int t = 0; t < 8; ++t) {
        int c = tid + t * 256;
        float y = w[c] * loc[t] * inv;
        float hi, lo;
        tf32splitf(y, hi, lo);
        g_xnH[(size_t)row * H + c] = hi;
        g_xnL[(size_t)row * H + c] = lo;
    }
}

// ------------------------------ rmsnorm (MoE input) -------------------------
__global__ void rmsnorm_moe_kernel(const float* __restrict__ n3) {
    int row = blockIdx.x;
    int tid = threadIdx.x;
    const float* xr = g_hidden + (size_t)row * H;
    float ss = 0.f;
    float2 loc[4];
#pragma unroll
    for (int t = 0; t < 4; ++t) {
        float2 v = *(const float2*)&xr[(tid + t * 256) * 2];
        loc[t] = v;
        ss += v.x * v.x + v.y * v.y;
    }
    __shared__ float red[256];
    red[tid] = ss;
    __syncthreads();
    for (int s2 = 128; s2 > 0; s2 >>= 1) {
        if (tid < s2) red[tid] += red[tid + s2];
        __syncthreads();
    }
    float inv = rsqrtf(red[0] / (float)H + EPS);
#pragma unroll
    for (int t = 0; t < 4; ++t) {
        int c = (tid + t * 256) * 2;
        float y0 = n3[c] * loc[t].x * inv;
        float y1 = n3[c + 1] * loc[t].y * inv;
        size_t idx = (size_t)row * H + c;
        *(float2*)&g_xnorm[idx] = make_float2(y0, y1);
        unsigned p0, p1;
        bfsplit2(y0, y1, p0, p1);
        ((unsigned*)g_xnB0)[idx >> 1] = p0;
        ((unsigned*)g_xnB1)[idx >> 1] = p1;
    }
}

__global__ void add_rmsnorm_kernel(const float* __restrict__ residual,
                                   const float* __restrict__ w) {
    int row = blockIdx.x;
    int tid = threadIdx.x;
    const float* xr = g_attnproj + (size_t)row * H;
    float ss = 0.f;
    float loc[8];
#pragma unroll
    for (int t = 0; t < 8; ++t) {
        float v = xr[tid + t * 256];
        loc[t] = v;
        ss += v * v;
    }
    __shared__ float red[256];
    red[tid] = ss;
    __syncthreads();
    for (int s2 = 128; s2 > 0; s2 >>= 1) {
        if (tid < s2) red[tid] += red[tid + s2];
        __syncthreads();
    }
    float inv = rsqrtf(red[0] / (float)H + EPS);
#pragma unroll
    for (int t = 0; t < 8; ++t) {
        int c = tid + t * 256;
        g_hidden[(size_t)row * H + c] =
            residual[(size_t)row * H + c] + w[c] * loc[t] * inv;
    }
}

__global__ void final_kernel(const float* __restrict__ n4,
                             float* __restrict__ out) {
    int t = blockIdx.x;
    int tid = threadIdx.x;
    int r0 = g_tok2row[2 * t], r1 = g_tok2row[2 * t + 1];
    float w0 = g_topw[2 * t], w1 = g_topw[2 * t + 1];
    const float* a = g_gout + (size_t)r0 * H;
    const float* b = g_gout + (size_t)r1 * H;
    float ss = 0.f;
    float loc[8];
#pragma unroll
    for (int k = 0; k < 8; ++k) {
        int c = tid + k * 256;
        float v = w0 * a[c] + w1 * b[c];
        loc[k] = v;
        ss += v * v;
    }
    __shared__ float red[256];
    red[tid] = ss;
    __syncthreads();
    for (int s2 = 128; s2 > 0; s2 >>= 1) {
        if (tid < s2) red[tid] += red[tid + s2];
        __syncthreads();
    }
    float inv = rsqrtf(red[0] / (float)H + EPS);
#pragma unroll
    for (int k = 0; k < 8; ++k) {
        int c = tid + k * 256;
        out[(size_t)t * H + c] = g_hidden[(size_t)t * H + c] + n4[c] * loc[k] * inv;
    }
}

// ---------------- fused prep: rope+split Q, rope+split K, split V ------------
#define QW (S * NH * 32)
#define KW (S * NKV * 32)
#define VW (S * NKV * D)

__global__ void prep_kernel() {
    int idx = blockIdx.x * blockDim.x + threadIdx.x;
    if (idx < QW + KW) {
        const float* x;
        float *xH, *xL;
        int nheads, i2;
        if (idx < QW) {
            x = g_q; xH = g_qH; xL = g_qL; nheads = NH; i2 = idx;
        } else {
            x = g_k; xH = g_kH; xL = g_kL; nheads = NKV; i2 = idx - QW;
        }
        int j = i2 & 31;
        int rest = i2 >> 5;
        int hh = rest % nheads;
        int s = rest / nheads;
        float inv = powf(10000.f, -(2.f * (float)j) / 64.f);
        float ph = (float)s * inv;
        float sn, cs;
        sincosf(ph, &sn, &cs);
        size_t base = ((size_t)s * nheads + hh) * 64 + j;
        float x1 = x[base], x2 = x[base + 32];
        float o1 = x1 * cs - x2 * sn;
        float o2 = x2 * cs + x1 * sn;
        float hi, lo;
        tf32splitf(o1, hi, lo);
        xH[base] = hi; xL[base] = lo;
        tf32splitf(o2, hi, lo);
        xH[base + 32] = hi; xL[base + 32] = lo;
    } else {
        int i2 = idx - QW - KW;
        if (i2 < VW) {
            float hi, lo;
            tf32splitf(g_v[i2], hi, lo);
            g_vH[i2] = hi;
            g_vL[i2] = lo;
        }
    }
}

// ------------------------------ router --------------------------------------
__global__ void router_kernel(const float* __restrict__ W,
                              float* __restrict__ logits_out) {
    const float* xf = g_xnorm;
    int t = blockIdx.x;
    int tid = threadIdx.x;
    int lane = tid & 31, warp = tid >> 5;
    float acc[E];
#pragma unroll
    for (int e = 0; e < E; ++e) acc[e] = 0.f;
    for (int hh = tid; hh < H; hh += 256) {
        float xv = xf[(size_t)t * H + hh];
        const float* wr = W + (size_t)hh * E;
#pragma unroll
        for (int e = 0; e < E; ++e) acc[e] += xv * wr[e];
    }
#pragma unroll
    for (int e = 0; e < E; ++e)
#pragma unroll
        for (int off = 16; off > 0; off >>= 1)
            acc[e] += __shfl_xor_sync(0xffffffffu, acc[e], off);
    __shared__ float wsum[8][E];
    __shared__ float logit[E];
    if (lane == 0)
#pragma unroll
        for (int e = 0; e < E; ++e) wsum[warp][e] = acc[e];
    __syncthreads();
    if (tid < E) {
        float s2 = 0.f;
        for (int w = 0; w < 8; ++w) s2 += wsum[w][tid];
        logit[tid] = s2;
        if (logits_out) logits_out[(size_t)t * E + tid] = s2;
    }
    __syncthreads();
    if (tid == 0) {
        float mx = logit[0];
        for (int e = 1; e < E; ++e) mx = fmaxf(mx, logit[e]);
        float ex[E], se = 0.f;
        for (int e = 0; e < E; ++e) {
            ex[e] = __expf(logit[e] - mx);
            se += ex[e];
        }
        int i0 = 0;
        for (int e = 1; e < E; ++e)
            if (ex[e] > ex[i0]) i0 = e;
        int i1 = (i0 == 0) ? 1 : 0;
        for (int e = 0; e < E; ++e)
            if (e != i0 && ex[e] > ex[i1]) i1 = e;
        float p0 = ex[i0] / se, p1 = ex[i1] / se;
        float inv2 = 1.f / (p0 + p1);
        g_topi[2 * t] = i0;
        g_topw[2 * t] = p0 * inv2;
        g_topi[2 * t + 1] = i1;
        g_topw[2 * t + 1] = p1 * inv2;
    }
}

// Parallel deterministic plan
__global__ void plan_kernel() {
    __shared__ int cnt[256][E];
    __shared__ int sbase[E];
    int t = threadIdx.x;
    int myi[8];
    int loc[E];
#pragma unroll
    for (int e = 0; e < E; ++e) loc[e] = 0;
#pragma unroll
    for (int j = 0; j < 8; ++j) {
        int a = t * 8 + j;
        int e = g_topi[a];
        myi[j] = e;
#pragma unroll
        for (int q = 0; q < E; ++q) loc[q] += (e == q) ? 1 : 0;
    }
#pragma unroll
    for (int e = 0; e < E; ++e) cnt[t][e] = loc[e];
    __syncthreads();
    if (t < E) {
        int run = 0;
        for (int i = 0; i < 256; ++i) {
            int c = cnt[i][t];
            cnt[i][t] = run;
            run += c;
        }
        sbase[t] = run;
    }
    __syncthreads();
    if (t == 0) {
        int off = 0;
        for (int e = 0; e < E; ++e) {
            g_offs[e] = off;
            int c = sbase[e];
            sbase[e] = off;
            off += c;
        }
        g_offs[E] = off;
    }
    __syncthreads();
    int run[E];
#pragma unroll
    for (int e = 0; e < E; ++e) run[e] = sbase[e] + cnt[t][e];
#pragma unroll
    for (int j = 0; j < 8; ++j) {
        int a = t * 8 + j;
        int e = myi[j];
        int pos = 0;
#pragma unroll
        for (int q = 0; q < E; ++q)
            if (e == q) { pos = run[q]; run[q] = pos + 1; }
        g_perm_token[pos] = a >> 1;
        g_tok2row[a] = pos;
    }
}

// ------------------------------ launch --------------------------------------
extern "C" void kernel_launch(void* const* d_in, const int* in_sizes, int n_in,
                              void* d_out, int out_size) {
    const float* hs = (const float*)d_in[0];
    const float* wq = (const float*)d_in[2];
    const float* wk = (const float*)d_in[3];
    const float* wv = (const float*)d_in[4];
    const float* wo = (const float*)d_in[5];
    const float* n1 = (const float*)d_in[6];
    const float* n2 = (const float*)d_in[7];
    const float* n3 = (const float*)d_in[8];
    const float* n4 = (const float*)d_in[9];
    const float* router = (const float*)d_in[10];
    const float* we_w1 = (const float*)d_in[11];
    const float* we_v = (const float*)d_in[12];
    const float* we_d = (const float*)d_in[13];
    float* out = (float*)d_out;
    float* logits_out = (out_size >= S * H + S * E) ? out + (size_t)S * H : nullptr;

    cudaFuncSetAttribute(flashmma_kernel,
                         cudaFuncAttributeMaxDynamicSharedMemorySize, FSM_BYTES);
    cudaFuncSetAttribute(tgemm_qkv_kernel,
                         cudaFuncAttributeMaxDynamicSharedMemorySize, SMEM_TF);
    cudaFuncSetAttribute(tgemm_wo_kernel,
                         cudaFuncAttributeMaxDynamicSharedMemorySize, SMEM_TF);
    cudaFuncSetAttribute(bgemm_group_kernel,
                         cudaFuncAttributeMaxDynamicSharedMemorySize, SMEM_BF);

    // 1. attention input norm -> tf32 planes
    rmsnorm_attn_kernel<<<S, 256>>>(hs, n1);

    // 2. fused q/k/v projection (3xtf32)
    tgemm_qkv_kernel<<<dim3(24, 8), 256, SMEM_TF>>>(wq, wk, wv);

    // 3. fused RoPE+split (Q, K) + V split
    prep_kernel<<<(QW + KW + VW + 255) / 256, 256>>>();

    // 4. tensor-core flash attention -> attn planes
    flashmma_kernel<<<dim3(8, NH), 256, FSM_BYTES>>>();

    // 5. output proj (3xtf32) + residual rmsnorm -> g_hidden
    tgemm_wo_kernel<<<dim3(16, 8), 256, SMEM_TF>>>(wo);
    add_rmsnorm_kernel<<<S, 256>>>(hs, n2);

    // 6. MoE input norm -> fp32 (router) + bf16 split planes
    rmsnorm_moe_kernel<<<S, 256>>>(n3);

    // 7. routing + parallel plan
    router_kernel<<<S, 256>>>(router, logits_out);
    plan_kernel<<<1, 256>>>();

    // 8. expert GEMMs (bf16x2-split, LDSM A, m-tail guard)
    bgemm_group_kernel<<<dim3(F / 128, 8, E), 256, SMEM_BF>>>(we_w1, 0);
    bgemm_group_kernel<<<dim3(F / 128, 8, E), 256, SMEM_BF>>>(we_v, 1);
    bgemm_group_kernel<<<dim3(H / 128, 8, E), 256, SMEM_BF>>>(we_d, 2);

    // 9. combine + final residual rmsnorm
    final_kernel<<<S, 256>>>(n4, out);
}

// round 17
// speedup vs baseline: 1.0167x; 1.0167x over previous
#include <cuda_runtime.h>
#include <cuda_bf16.h>
#include <math.h>

// ---------------------------------------------------------------------------
// Decoder layer, round 17 (= R15 + BK=32 for attention-path tf32 GEMMs):
//  - attention-path GEMMs (QKV, WO): 3xtf32 2-stage, LDSM A, BK=32
//  - flash attention: R13 structure, LDSM Q
//  - MoE expert GEMMs: 2-plane bf16 split, LDSM A (exact R15)
// Scratch accessed ONLY as device symbols inside kernels (ATS trap).
// ---------------------------------------------------------------------------

#define S 1024
#define H 2048
#define NH 32
#define NKV 8
#define D 64
#define E 8
#define TOPK 2
#define F 4096
#define EPS 1e-5f
#define MULT 0.125f
#define CAP 30.0f

// ------------------------------ scratch (device globals) --------------------
__device__ float g_xnH[S * H];
__device__ float g_xnL[S * H];
__device__ float g_xnorm[S * H];
__device__ __nv_bfloat16 g_xnB0[S * H];
__device__ __nv_bfloat16 g_xnB1[S * H];
__device__ float g_attnH[S * H];
__device__ float g_attnL[S * H];
__device__ float g_q[S * NH * D];
__device__ float g_k[S * NKV * D];
__device__ float g_v[S * NKV * D];
__device__ float g_qH[S * NH * D];
__device__ float g_qL[S * NH * D];
__device__ float g_kH[S * NKV * D];
__device__ float g_kL[S * NKV * D];
__device__ float g_vH[S * NKV * D];
__device__ float g_vL[S * NKV * D];
__device__ float g_attnproj[S * H];
__device__ float g_hidden[S * H];
__device__ float g_h1[S * TOPK * F];
__device__ __nv_bfloat16 g_h1B0[S * TOPK * F];
__device__ __nv_bfloat16 g_h1B1[S * TOPK * F];
__device__ float g_gout[S * TOPK * H];
__device__ int   g_topi[S * TOPK];
__device__ float g_topw[S * TOPK];
__device__ int   g_offs[E + 1];
__device__ int   g_perm_token[S * TOPK];
__device__ int   g_tok2row[S * TOPK];

// ------------------------------ numeric helpers -----------------------------
__device__ __forceinline__ float f2tf32f(float x) {
    unsigned r;
    asm("cvt.rna.tf32.f32 %0, %1;" : "=r"(r) : "f"(x));
    return __uint_as_float(r);
}
__device__ __forceinline__ void tf32splitf(float x, float& hi, float& lo) {
    hi = f2tf32f(x);
    lo = f2tf32f(x - hi);
}
__device__ __forceinline__ void mma_tf32(float c[4], const unsigned a[4],
                                         const unsigned b[2]) {
    asm volatile(
        "mma.sync.aligned.m16n8k8.row.col.f32.tf32.tf32.f32 "
        "{%0,%1,%2,%3}, {%4,%5,%6,%7}, {%8,%9}, {%0,%1,%2,%3};"
        : "+f"(c[0]), "+f"(c[1]), "+f"(c[2]), "+f"(c[3])
        : "r"(a[0]), "r"(a[1]), "r"(a[2]), "r"(a[3]), "r"(b[0]), "r"(b[1]));
}
__device__ __forceinline__ void mma_bf16(float c[4], const unsigned a[4],
                                         const unsigned b[2]) {
    asm volatile(
        "mma.sync.aligned.m16n8k16.row.col.f32.bf16.bf16.f32 "
        "{%0,%1,%2,%3}, {%4,%5,%6,%7}, {%8,%9}, {%0,%1,%2,%3};"
        : "+f"(c[0]), "+f"(c[1]), "+f"(c[2]), "+f"(c[3])
        : "r"(a[0]), "r"(a[1]), "r"(a[2]), "r"(a[3]), "r"(b[0]), "r"(b[1]));
}
__device__ __forceinline__ void ldsm4(unsigned r[4], unsigned saddr) {
    asm volatile(
        "ldmatrix.sync.aligned.m8n8.x4.shared.b16 {%0,%1,%2,%3}, [%4];"
        : "=r"(r[0]), "=r"(r[1]), "=r"(r[2]), "=r"(r[3]) : "r"(saddr));
}
__device__ __forceinline__ unsigned packbf(float x0, float x1) {
    unsigned d;
    asm("cvt.rn.bf16x2.f32 %0, %1, %2;" : "=r"(d) : "f"(x1), "f"(x0));
    return d;
}
__device__ __forceinline__ void bfsplit2(float x0, float x1,
                                         unsigned& p0, unsigned& p1) {
    unsigned h = packbf(x0, x1);
    float r0 = x0 - __uint_as_float(h << 16);
    float r1 = x1 - __uint_as_float(h & 0xffff0000u);
    p0 = h;
    p1 = packbf(r0, r1);
}
__device__ __forceinline__ void cpa16(unsigned dst, const void* src, bool valid) {
    int sz = valid ? 16 : 0;
    asm volatile("cp.async.ca.shared.global [%0], [%1], 16, %2;\n"
                 :: "r"(dst), "l"(src), "r"(sz));
}
__device__ __forceinline__ float tanh_fast(float x) {
    float z = __expf(-2.f * fabsf(x));
    float th = __fdividef(1.f - z, 1.f + z);
    return copysignf(th, x);
}

// ======================= tf32 GEMM (attention path, BK=32) ==================
// smem/stage floats: AH 128*36=4608 | AL 4608 | B 32*132=4224 -> 13440
#define STG 13440
#define SMEM_TF (2 * STG * 4)

struct Ctx {
    const float *AH, *AL;
    const float *B;
    float* C;
    int N, K;
    int nBase;
    int mBase, rend;
};

__device__ __forceinline__ void stage_tf(const Ctx& g, float* sm, int sbuf,
                                         int k0, int tid) {
    unsigned base = (unsigned)__cvta_generic_to_shared(sm + sbuf * STG);
    // A planes: 128 rows x 32 cols = 1024 16B-chunks per plane
#pragma unroll
    for (int i = 0; i < 4; ++i) {
        int idx = tid + i * 256;          // 0..1023
        int row = idx >> 3, c4 = (idx & 7) * 4;
        int grow = g.mBase + row;
        bool valid = grow < g.rend;
        size_t off = (size_t)(valid ? grow : 0) * g.K + k0 + c4;
        unsigned d = base + (unsigned)(row * 36 + c4) * 4;
        cpa16(d, g.AH + off, valid);
        cpa16(d + 4608 * 4, g.AL + off, valid);
    }
    // B: 32 rows x 128 cols = 1024 16B-chunks
#pragma unroll
    for (int i = 0; i < 4; ++i) {
        int idx = tid + i * 256;          // 0..1023
        int row = idx >> 5, c4 = (idx & 31) * 4;
        size_t off = (size_t)(k0 + row) * g.N + g.nBase + c4;
        unsigned d = base + (unsigned)(9216 + row * 132 + c4) * 4;
        cpa16(d, g.B + off, true);
    }
    asm volatile("cp.async.commit_group;" ::: "memory");
}

__device__ __forceinline__ void gemm_tf(const Ctx& g) {
    extern __shared__ float sm[];
    int tid = threadIdx.x;
    int lane = tid & 31, warp = tid >> 5;
    int wr = warp & 1, wc = warp >> 1;
    int mW = wr * 64, nW = wc * 32;
    int gid = lane >> 2, tig = lane & 3;
    int rowsel = ((lane >> 3) & 1) * 8 + (lane & 7);
    int ksel = (lane >> 4) * 4;

    float acc[4][4][4];
#pragma unroll
    for (int mt = 0; mt < 4; ++mt)
#pragma unroll
        for (int nt = 0; nt < 4; ++nt)
#pragma unroll
            for (int r = 0; r < 4; ++r) acc[mt][nt][r] = 0.f;

    int niters = g.K / 32;
    stage_tf(g, sm, 0, 0, tid);

    for (int it = 0; it < niters; ++it) {
        int cur = it & 1;
        if (it + 1 < niters) {
            stage_tf(g, sm, cur ^ 1, (it + 1) * 32, tid);
            asm volatile("cp.async.wait_group 1;" ::: "memory");
        } else {
            asm volatile("cp.async.wait_group 0;" ::: "memory");
        }
        __syncthreads();

        const float* AHs = sm + cur * STG;
        const float* Bs = AHs + 9216;
        unsigned aBase = (unsigned)__cvta_generic_to_shared(AHs);
#pragma unroll
        for (int kk = 0; kk < 32; kk += 8) {
            unsigned bH[4][2], bL[4][2];
#pragma unroll
            for (int nt = 0; nt < 4; ++nt) {
                int c0 = (kk + tig) * 132 + nW + nt * 8 + gid;
                int c1 = c0 + 528;
                float h0, l0, h1, l1;
                tf32splitf(Bs[c0], h0, l0);
                tf32splitf(Bs[c1], h1, l1);
                bH[nt][0] = __float_as_uint(h0);
                bL[nt][0] = __float_as_uint(l0);
                bH[nt][1] = __float_as_uint(h1);
                bL[nt][1] = __float_as_uint(l1);
            }
#pragma unroll
            for (int mt = 0; mt < 4; ++mt) {
                unsigned off =
                    (unsigned)(((mW + mt * 16 + rowsel) * 36 + kk + ksel) * 4);
                unsigned aH[4], aL[4];
                ldsm4(aH, aBase + off);
                ldsm4(aL, aBase + 4608 * 4 + off);
#pragma unroll
                for (int nt = 0; nt < 4; ++nt) {
                    mma_tf32(acc[mt][nt], aH, bL[nt]);
                    mma_tf32(acc[mt][nt], aL, bH[nt]);
                    mma_tf32(acc[mt][nt], aH, bH[nt]);
                }
            }
        }
        __syncthreads();
    }

#pragma unroll
    for (int mt = 0; mt < 4; ++mt) {
#pragma unroll
        for (int half = 0; half < 2; ++half) {
            int r0 = g.mBase + mW + mt * 16 + gid + half * 8;
            if (r0 >= g.rend) continue;
#pragma unroll
            for (int nt = 0; nt < 4; ++nt) {
                int col = g.nBase + nW + nt * 8 + tig * 2;
                *(float2*)&g.C[(size_t)r0 * g.N + col] =
                    make_float2(acc[mt][nt][half * 2], acc[mt][nt][half * 2 + 1]);
            }
        }
    }
}

__global__ void __launch_bounds__(256, 2) tgemm_qkv_kernel(
    const float* __restrict__ wq, const float* __restrict__ wk,
    const float* __restrict__ wv) {
    int bx = blockIdx.x;
    Ctx g;
    g.AH = g_xnH; g.AL = g_xnL;
    g.K = H;
    g.mBase = blockIdx.y * 128;
    g.rend = S;
    if (bx < 16) {
        g.B = wq; g.C = g_q; g.N = 2048; g.nBase = bx * 128;
    } else if (bx < 20) {
        g.B = wk; g.C = g_k; g.N = 512; g.nBase = (bx - 16) * 128;
    } else {
        g.B = wv; g.C = g_v; g.N = 512; g.nBase = (bx - 20) * 128;
    }
    gemm_tf(g);
}

__global__ void __launch_bounds__(256, 2) tgemm_wo_kernel(
    const float* __restrict__ wo) {
    Ctx g;
    g.AH = g_attnH; g.AL = g_attnL;
    g.B = wo;
    g.C = g_attnproj;
    g.N = H; g.K = H;
    g.nBase = blockIdx.x * 128;
    g.mBase = blockIdx.y * 128;
    g.rend = S;
    gemm_tf(g);
}

// ======================= bf16x2-split GEMM (MoE path, exact R15) ============
#define BSTG 37376
#define SMEM_BF (2 * BSTG)

__global__ void __launch_bounds__(256, 2) bgemm_group_kernel(
    const float* __restrict__ W, int which) {
    int e = blockIdx.z;
    int rbeg = g_offs[e], rend = g_offs[e + 1];
    int mBase = rbeg + blockIdx.y * 128;
    if (mBase >= rend) return;

    const __nv_bfloat16 *A0, *A1;
    const float* B;
    float* C;
    int N, K, useGather, epi;
    if (which == 2) {
        A0 = g_h1B0; A1 = g_h1B1; useGather = 0; epi = 0;
        B = W + (size_t)e * F * H; C = g_gout; N = H; K = F;
    } else {
        A0 = g_xnB0; A1 = g_xnB1; useGather = 1; epi = which;
        B = W + (size_t)e * H * F; C = g_h1; N = F; K = H;
    }
    int nBase = blockIdx.x * 128;

    extern __shared__ char smc[];
    int tid = threadIdx.x;
    int lane = tid & 31, warp = tid >> 5;
    int wr = warp & 1, wc = warp >> 1;
    int mW = wr * 64, nW = wc * 32;
    int gid = lane >> 2, tig = lane & 3;
    int rowsel = ((lane >> 3) & 1) * 8 + (lane & 7);
    int ksel16 = (lane >> 4) * 16;

    float acc[4][4][4];
#pragma unroll
    for (int mt = 0; mt < 4; ++mt)
#pragma unroll
        for (int nt = 0; nt < 4; ++nt)
#pragma unroll
            for (int r = 0; r < 4; ++r) acc[mt][nt][r] = 0.f;

    auto stage = [&](int sbuf, int k0) {
        unsigned base = (unsigned)__cvta_generic_to_shared(smc + sbuf * BSTG);
#pragma unroll
        for (int i = 0; i < 4; ++i) {
            int idx = tid + i * 256;
            int plane = idx >> 9;
            int rem = idx & 511;
            int row = rem >> 2, ch = rem & 3;
            int grow = mBase + row;
            bool valid = grow < rend;
            int arow = valid ? (useGather ? g_perm_token[grow] : grow) : 0;
            const __nv_bfloat16* src = (plane ? A1 : A0) + (size_t)arow * K + k0 + ch * 8;
            unsigned d = base + plane * 10240 + row * 80 + ch * 16;
            cpa16(d, src, valid);
        }
#pragma unroll
        for (int i = 0; i < 4; ++i) {
            int idx = tid + i * 256;
            int row = idx >> 5, ch = idx & 31;
            const float* src = B + (size_t)(k0 + row) * N + nBase + ch * 4;
            unsigned d = base + 20480 + row * 528 + ch * 16;
            cpa16(d, src, true);
        }
        asm volatile("cp.async.commit_group;" ::: "memory");
    };

    int niters = K / 32;
    stage(0, 0);
    for (int it = 0; it < niters; ++it) {
        int cur = it & 1;
        if (it + 1 < niters) {
            stage(cur ^ 1, (it + 1) * 32);
            asm volatile("cp.async.wait_group 1;" ::: "memory");
        } else {
            asm volatile("cp.async.wait_group 0;" ::: "memory");
        }
        __syncthreads();

        const char* sb = smc + cur * BSTG;
        const float* Bs = (const float*)(sb + 20480);
        unsigned aBase = (unsigned)__cvta_generic_to_shared(sb);
#pragma unroll
        for (int s = 0; s < 2; ++s) {
            unsigned bH[4][2], bL[4][2];
#pragma unroll
            for (int nt = 0; nt < 4; ++nt) {
                int c = nW + nt * 8 + gid;
                int rb = (s * 16 + 2 * tig) * 132 + c;
                bfsplit2(Bs[rb], Bs[rb + 132], bH[nt][0], bL[nt][0]);
                bfsplit2(Bs[rb + 8 * 132], Bs[rb + 9 * 132], bH[nt][1], bL[nt][1]);
            }
#pragma unroll
            for (int mt = 0; mt < 4; ++mt) {
                unsigned off =
                    (unsigned)((mW + mt * 16 + rowsel) * 80 + s * 32 + ksel16);
                unsigned aH[4], aL[4];
                ldsm4(aH, aBase + off);
                ldsm4(aL, aBase + 10240 + off);
#pragma unroll
                for (int nt = 0; nt < 4; ++nt) {
                    mma_bf16(acc[mt][nt], aH, bL[nt]);
                    mma_bf16(acc[mt][nt], aL, bH[nt]);
                    mma_bf16(acc[mt][nt], aH, bH[nt]);
                }
            }
        }
        __syncthreads();
    }

#pragma unroll
    for (int mt = 0; mt < 4; ++mt) {
#pragma unroll
        for (int half = 0; half < 2; ++half) {
            int r0 = mBase + mW + mt * 16 + gid + half * 8;
            if (r0 >= rend) continue;
#pragma unroll
            for (int nt = 0; nt < 4; ++nt) {
                int col = nBase + nW + nt * 8 + tig * 2;
                float v0 = acc[mt][nt][half * 2 + 0];
                float v1 = acc[mt][nt][half * 2 + 1];
                size_t idx = (size_t)r0 * N + col;
                if (epi == 0) {
                    *(float2*)&C[idx] = make_float2(v0, v1);
                } else {
                    float a0 = g_h1[idx], a1 = g_h1[idx + 1];
                    float ge0 = 0.5f * a0 * (1.f + erff(a0 * 0.7071067811865475f));
                    float ge1 = 0.5f * a1 * (1.f + erff(a1 * 0.7071067811865475f));
                    unsigned p0, p1;
                    bfsplit2(ge0 * v0, ge1 * v1, p0, p1);
                    ((unsigned*)g_h1B0)[idx >> 1] = p0;
                    ((unsigned*)g_h1B1)[idx >> 1] = p1;
                }
            }
        }
    }
}

// ======================= tensor-core flash attention (R15) ==================
#define FSM_BYTES 212992

__global__ void __launch_bounds__(256, 1) flashmma_kernel() {
    extern __shared__ float sm[];
    float* QH = sm;
    float* QL = sm + 8704;

    int qt = 7 - (int)blockIdx.x;
    int h = blockIdx.y;
    int kv = h >> 2;
    int tid = threadIdx.x;
    int lane = tid & 31, warp = tid >> 5;
    int gid = lane >> 2, tig = lane & 3;
    int qr0 = qt * 128;
    int srcA = (lane & ~3) | (tig >> 1);
    int srcB = srcA + 2;
    bool odd = (tig & 1);
    int rowsel = ((lane >> 3) & 1) * 8 + (lane & 7);
    int ksel = (lane >> 4) * 4;
    unsigned qBase = (unsigned)__cvta_generic_to_shared(QH);

    for (int i = tid; i < 128 * 64; i += 256) {
        int r = i >> 6, d = i & 63;
        size_t gi = (size_t)(qr0 + r) * (NH * D) + h * 64 + d;
        QH[r * 68 + d] = g_qH[gi];
        QL[r * 68 + d] = g_qL[gi];
    }

    auto stageKV = [&](int buf, int k0g) {
        float* bb = sm + 17408 + buf * 17920;
        unsigned base = (unsigned)__cvta_generic_to_shared(bb);
#pragma unroll
        for (int i = 0; i < 16; ++i) {
            int idx = tid + i * 256;
            int plane = idx >> 10;
            int rem = idx & 1023;
            int row = rem >> 4, ch = rem & 15;
            const float* srcp;
            unsigned dst;
            size_t so = (size_t)(k0g + row) * (NKV * D) + kv * 64 + ch * 4;
            if (plane == 0) { srcp = g_kH + so; dst = base + (row * 68 + ch * 4) * 4; }
            else if (plane == 1) { srcp = g_kL + so; dst = base + (4352 + row * 68 + ch * 4) * 4; }
            else if (plane == 2) { srcp = g_vH + so; dst = base + (8704 + row * 72 + ch * 4) * 4; }
            else { srcp = g_vL + so; dst = base + (13312 + row * 72 + ch * 4) * 4; }
            cpa16(dst, srcp, true);
        }
        asm volatile("cp.async.commit_group;" ::: "memory");
    };

    float mrow[2] = {-1e30f, -1e30f};
    float lrow[2] = {0.f, 0.f};
    float oacc[8][4];
#pragma unroll
    for (int nt = 0; nt < 8; ++nt)
#pragma unroll
        for (int c = 0; c < 4; ++c) oacc[nt][c] = 0.f;

    int nkt = 2 * qt + 2;
    stageKV(0, 0);
    for (int kt = 0; kt < nkt; ++kt) {
        int k0g = kt * 64;
        bool domask = (kt >= 2 * qt);
        __syncthreads();
        if (kt + 1 < nkt) {
            stageKV((kt + 1) & 1, (kt + 1) * 64);
            asm volatile("cp.async.wait_group 1;" ::: "memory");
        } else {
            asm volatile("cp.async.wait_group 0;" ::: "memory");
        }
        __syncthreads();

        const float* bb = sm + 17408 + (kt & 1) * 17920;
        const float* KsH = bb;
        const float* KsL = bb + 4352;
        const float* VsH = bb + 8704;
        const float* VsL = bb + 13312;

        float sacc[8][4];
#pragma unroll
        for (int nt = 0; nt < 8; ++nt)
#pragma unroll
            for (int c = 0; c < 4; ++c) sacc[nt][c] = 0.f;
#pragma unroll
        for (int kk = 0; kk < 64; kk += 8) {
            unsigned off =
                (unsigned)(((warp * 16 + rowsel) * 68 + kk + ksel) * 4);
            unsigned aH[4], aL[4];
            ldsm4(aH, qBase + off);
            ldsm4(aL, qBase + 8704 * 4 + off);
#pragma unroll
            for (int nt = 0; nt < 8; ++nt) {
                int kb = (nt * 8 + gid) * 68 + kk + tig;
                unsigned bH[2], bL[2];
                bH[0] = __float_as_uint(KsH[kb]);
                bH[1] = __float_as_uint(KsH[kb + 4]);
                bL[0] = __float_as_uint(KsL[kb]);
                bL[1] = __float_as_uint(KsL[kb + 4]);
                mma_tf32(sacc[nt], aH, bL);
                mma_tf32(sacc[nt], aL, bH);
                mma_tf32(sacc[nt], aH, bH);
            }
        }

#pragma unroll
        for (int nt = 0; nt < 8; ++nt)
#pragma unroll
            for (int c = 0; c < 4; ++c) {
                float v = CAP * tanh_fast(sacc[nt][c] * (MULT / CAP));
                if (domask) {
                    int row = qr0 + warp * 16 + gid + (c >> 1) * 8;
                    int key = k0g + nt * 8 + tig * 2 + (c & 1);
                    if (key > row) v = -1e30f;
                }
                sacc[nt][c] = v;
            }

#pragma unroll
        for (int half = 0; half < 2; ++half) {
            float rm = -1e30f;
#pragma unroll
            for (int nt = 0; nt < 8; ++nt)
                rm = fmaxf(rm, fmaxf(sacc[nt][half * 2], sacc[nt][half * 2 + 1]));
            rm = fmaxf(rm, __shfl_xor_sync(0xffffffffu, rm, 1));
            rm = fmaxf(rm, __shfl_xor_sync(0xffffffffu, rm, 2));
            float mn = fmaxf(mrow[half], rm);
            float scl = __expf(mrow[half] - mn);
            float rs = 0.f;
#pragma unroll
            for (int nt = 0; nt < 8; ++nt) {
                float p0 = __expf(sacc[nt][half * 2] - mn);
                float p1 = __expf(sacc[nt][half * 2 + 1] - mn);
                sacc[nt][half * 2] = p0;
                sacc[nt][half * 2 + 1] = p1;
                rs += p0 + p1;
            }
            rs += __shfl_xor_sync(0xffffffffu, rs, 1);
            rs += __shfl_xor_sync(0xffffffffu, rs, 2);
            lrow[half] = lrow[half] * scl + rs;
            mrow[half] = mn;
#pragma unroll
            for (int nt = 0; nt < 8; ++nt) {
                oacc[nt][half * 2] *= scl;
                oacc[nt][half * 2 + 1] *= scl;
            }
        }

#pragma unroll
        for (int kk = 0; kk < 64; kk += 8) {
            int ntp = kk >> 3;
            float v00 = sacc[ntp][0], v01 = sacc[ntp][1];
            float v10 = sacc[ntp][2], v11 = sacc[ntp][3];
            float s00a = __shfl_sync(0xffffffffu, v00, srcA);
            float s01a = __shfl_sync(0xffffffffu, v01, srcA);
            float s10a = __shfl_sync(0xffffffffu, v10, srcA);
            float s11a = __shfl_sync(0xffffffffu, v11, srcA);
            float s00b = __shfl_sync(0xffffffffu, v00, srcB);
            float s01b = __shfl_sync(0xffffffffu, v01, srcB);
            float s10b = __shfl_sync(0xffffffffu, v10, srcB);
            float s11b = __shfl_sync(0xffffffffu, v11, srcB);
            float a0 = odd ? s01a : s00a;
            float a1 = odd ? s11a : s10a;
            float a2 = odd ? s01b : s00b;
            float a3 = odd ? s11b : s10b;
            unsigned aH[4], aL[4];
            float hi, lo;
            tf32splitf(a0, hi, lo); aH[0] = __float_as_uint(hi); aL[0] = __float_as_uint(lo);
            tf32splitf(a1, hi, lo); aH[1] = __float_as_uint(hi); aL[1] = __float_as_uint(lo);
            tf32splitf(a2, hi, lo); aH[2] = __float_as_uint(hi); aL[2] = __float_as_uint(lo);
            tf32splitf(a3, hi, lo); aH[3] = __float_as_uint(hi); aL[3] = __float_as_uint(lo);
#pragma unroll
            for (int nt = 0; nt < 8; ++nt) {
                int vb = (kk + tig) * 72 + nt * 8 + gid;
                int vb4 = vb + 4 * 72;
                unsigned bH[2], bL[2];
                bH[0] = __float_as_uint(VsH[vb]);
                bH[1] = __float_as_uint(VsH[vb4]);
                bL[0] = __float_as_uint(VsL[vb]);
                bL[1] = __float_as_uint(VsL[vb4]);
                mma_tf32(oacc[nt], aH, bL);
                mma_tf32(oacc[nt], aL, bH);
                mma_tf32(oacc[nt], aH, bH);
            }
        }
    }

#pragma unroll
    for (int half = 0; half < 2; ++half) {
        float invl = 1.f / lrow[half];
        int row = qr0 + warp * 16 + gid + half * 8;
#pragma unroll
        for (int nt = 0; nt < 8; ++nt) {
            float o0 = oacc[nt][half * 2] * invl;
            float o1 = oacc[nt][half * 2 + 1] * invl;
            float h0, l0, h1, l1;
            tf32splitf(o0, h0, l0);
            tf32splitf(o1, h1, l1);
            size_t idx = (size_t)row * H + h * 64 + nt * 8 + tig * 2;
            *(float2*)&g_attnH[idx] = make_float2(h0, h1);
            *(float2*)&g_attnL[idx] = make_float2(l0, l1);
        }
    }
}

// ------------------------------ rmsnorm (attention input) -------------------
__global__ void rmsnorm_attn_kernel(const float* __restrict__ x,
                                    const float* __restrict__ w) {
    int row = blockIdx.x;
    int tid = threadIdx.x;
    const float* xr = x + (size_t)row * H;
    float ss = 0.f;
    float loc[8];
#pragma unroll
    for (int t = 0; t < 8; ++t) {
        float v = xr[tid + t * 256];
        loc[t] = v;
        ss += v * v;
    }
    __shared__ float red[256];
    red[tid] = ss;
    __syncthreads();
    for (int s2 = 128; s2 > 0; s2 >>= 1) {
        if (tid < s2) red[tid] += red[tid + s2];
        __syncthreads();
    }
    float inv = rsqrtf(red[0] / (float)H + EPS);
#pragma unroll
    for (int t = 0; t < 8; ++t) {
        int c = tid + t * 256;
        float y = w[c] * loc[t] * inv;
        float hi, lo;
        tf32splitf(y, hi, lo);
        g_xnH[(size_t)row * H + c] = hi;
        g_xnL[(size_t)row * H + c] = lo;
    }
}

// ------------------------------ rmsnorm (MoE input) -------------------------
__global__ void rmsnorm_moe_kernel(const float* __restrict__ n3) {
    int row = blockIdx.x;
    int tid = threadIdx.x;
    const float* xr = g_hidden + (size_t)row * H;
    float ss = 0.f;
    float2 loc[4];
#pragma unroll
    for (int t = 0; t < 4; ++t) {
        float2 v = *(const float2*)&xr[(tid + t * 256) * 2];
        loc[t] = v;
        ss += v.x * v.x + v.y * v.y;
    }
    __shared__ float red[256];
    red[tid] = ss;
    __syncthreads();
    for (int s2 = 128; s2 > 0; s2 >>= 1) {
        if (tid < s2) red[tid] += red[tid + s2];
        __syncthreads();
    }
    float inv = rsqrtf(red[0] / (float)H + EPS);
#pragma unroll
    for (int t = 0; t < 4; ++t) {
        int c = (tid + t * 256) * 2;
        float y0 = n3[c] * loc[t].x * inv;
        float y1 = n3[c + 1] * loc[t].y * inv;
        size_t idx = (size_t)row * H + c;
        *(float2*)&g_xnorm[idx] = make_float2(y0, y1);
        unsigned p0, p1;
        bfsplit2(y0, y1, p0, p1);
        ((unsigned*)g_xnB0)[idx >> 1] = p0;
        ((unsigned*)g_xnB1)[idx >> 1] = p1;
    }
}

__global__ void add_rmsnorm_kernel(const float* __restrict__ residual,
                                   const float* __restrict__ w) {
    int row = blockIdx.x;
    int tid = threadIdx.x;
    const float* xr = g_attnproj + (size_t)row * H;
    float ss = 0.f;
    float loc[8];
#pragma unroll
    for (int t = 0; t < 8; ++t) {
        float v = xr[tid + t * 256];
        loc[t] = v;
        ss += v * v;
    }
    __shared__ float red[256];
    red[tid] = ss;
    __syncthreads();
    for (int s2 = 128; s2 > 0; s2 >>= 1) {
        if (tid < s2) red[tid] += red[tid + s2];
        __syncthreads();
    }
    float inv = rsqrtf(red[0] / (float)H + EPS);
#pragma unroll
    for (int t = 0; t < 8; ++t) {
        int c = tid + t * 256;
        g_hidden[(size_t)row * H + c] =
            residual[(size_t)row * H + c] + w[c] * loc[t] * inv;
    }
}

__global__ void final_kernel(const float* __restrict__ n4,
                             float* __restrict__ out) {
    int t = blockIdx.x;
    int tid = threadIdx.x;
    int r0 = g_tok2row[2 * t], r1 = g_tok2row[2 * t + 1];
    float w0 = g_topw[2 * t], w1 = g_topw[2 * t + 1];
    const float* a = g_gout + (size_t)r0 * H;
    const float* b = g_gout + (size_t)r1 * H;
    float ss = 0.f;
    float loc[8];
#pragma unroll
    for (int k = 0; k < 8; ++k) {
        int c = tid + k * 256;
        float v = w0 * a[c] + w1 * b[c];
        loc[k] = v;
        ss += v * v;
    }
    __shared__ float red[256];
    red[tid] = ss;
    __syncthreads();
    for (int s2 = 128; s2 > 0; s2 >>= 1) {
        if (tid < s2) red[tid] += red[tid + s2];
        __syncthreads();
    }
    float inv = rsqrtf(red[0] / (float)H + EPS);
#pragma unroll
    for (int k = 0; k < 8; ++k) {
        int c = tid + k * 256;
        out[(size_t)t * H + c] = g_hidden[(size_t)t * H + c] + n4[c] * loc[k] * inv;
    }
}

// ------------------------------ RoPE + split --------------------------------
__global__ void rope_split_kernel(int isQ, int nheads) {
    const float* x = isQ ? g_q : g_k;
    float* xH = isQ ? g_qH : g_kH;
    float* xL = isQ ? g_qL : g_kL;
    int idx = blockIdx.x * blockDim.x + threadIdx.x;
    int total = S * nheads * 32;
    if (idx >= total) return;
    int j = idx & 31;
    int rest = idx >> 5;
    int hh = rest % nheads;
    int s = rest / nheads;
    float inv = powf(10000.f, -(2.f * (float)j) / 64.f);
    float ph = (float)s * inv;
    float sn, cs;
    sincosf(ph, &sn, &cs);
    size_t base = ((size_t)s * nheads + hh) * 64 + j;
    float x1 = x[base], x2 = x[base + 32];
    float o1 = x1 * cs - x2 * sn;
    float o2 = x2 * cs + x1 * sn;
    float hi, lo;
    tf32splitf(o1, hi, lo);
    xH[base] = hi; xL[base] = lo;
    tf32splitf(o2, hi, lo);
    xH[base + 32] = hi; xL[base + 32] = lo;
}

__global__ void vsplit_kernel() {
    int idx = blockIdx.x * blockDim.x + threadIdx.x;
    if (idx >= S * NKV * D) return;
    float hi, lo;
    tf32splitf(g_v[idx], hi, lo);
    g_vH[idx] = hi;
    g_vL[idx] = lo;
}

// ------------------------------ router --------------------------------------
__global__ void router_kernel(const float* __restrict__ W,
                              float* __restrict__ logits_out) {
    const float* xf = g_xnorm;
    int t = blockIdx.x;
    int tid = threadIdx.x;
    int lane = tid & 31, warp = tid >> 5;
    float acc[E];
#pragma unroll
    for (int e = 0; e < E; ++e) acc[e] = 0.f;
    for (int hh = tid; hh < H; hh += 256) {
        float xv = xf[(size_t)t * H + hh];
        const float* wr = W + (size_t)hh * E;
#pragma unroll
        for (int e = 0; e < E; ++e) acc[e] += xv * wr[e];
    }
#pragma unroll
    for (int e = 0; e < E; ++e)
#pragma unroll
        for (int off = 16; off > 0; off >>= 1)
            acc[e] += __shfl_xor_sync(0xffffffffu, acc[e], off);
    __shared__ float wsum[8][E];
    __shared__ float logit[E];
    if (lane == 0)
#pragma unroll
        for (int e = 0; e < E; ++e) wsum[warp][e] = acc[e];
    __syncthreads();
    if (tid < E) {
        float s2 = 0.f;
        for (int w = 0; w < 8; ++w) s2 += wsum[w][tid];
        logit[tid] = s2;
        if (logits_out) logits_out[(size_t)t * E + tid] = s2;
    }
    __syncthreads();
    if (tid == 0) {
        float mx = logit[0];
        for (int e = 1; e < E; ++e) mx = fmaxf(mx, logit[e]);
        float ex[E], se = 0.f;
        for (int e = 0; e < E; ++e) {
            ex[e] = __expf(logit[e] - mx);
            se += ex[e];
        }
        int i0 = 0;
        for (int e = 1; e < E; ++e)
            if (ex[e] > ex[i0]) i0 = e;
        int i1 = (i0 == 0) ? 1 : 0;
        for (int e = 0; e < E; ++e)
            if (e != i0 && ex[e] > ex[i1]) i1 = e;
        float p0 = ex[i0] / se, p1 = ex[i1] / se;
        float inv2 = 1.f / (p0 + p1);
        g_topi[2 * t] = i0;
        g_topw[2 * t] = p0 * inv2;
        g_topi[2 * t + 1] = i1;
        g_topw[2 * t + 1] = p1 * inv2;
    }
}

// Parallel deterministic plan
__global__ void plan_kernel() {
    __shared__ int cnt[256][E];
    __shared__ int sbase[E];
    int t = threadIdx.x;
    int myi[8];
    int loc[E];
#pragma unroll
    for (int e = 0; e < E; ++e) loc[e] = 0;
#pragma unroll
    for (int j = 0; j < 8; ++j) {
        int a = t * 8 + j;
        int e = g_topi[a];
        myi[j] = e;
#pragma unroll
        for (int q = 0; q < E; ++q) loc[q] += (e == q) ? 1 : 0;
    }
#pragma unroll
    for (int e = 0; e < E; ++e) cnt[t][e] = loc[e];
    __syncthreads();
    if (t < E) {
        int run = 0;
        for (int i = 0; i < 256; ++i) {
            int c = cnt[i][t];
            cnt[i][t] = run;
            run += c;
        }
        sbase[t] = run;
    }
    __syncthreads();
    if (t == 0) {
        int off = 0;
        for (int e = 0; e < E; ++e) {
            g_offs[e] = off;
            int c = sbase[e];
            sbase[e] = off;
            off += c;
        }
        g_offs[E] = off;
    }
    __syncthreads();
    int run[E];
#pragma unroll
    for (int e = 0; e < E; ++e) run[e] = sbase[e] + cnt[t][e];
#pragma unroll
    for (int j = 0; j < 8; ++j) {
        int a = t * 8 + j;
        int e = myi[j];
        int pos = 0;
#pragma unroll
        for (int q = 0; q < E; ++q)
            if (e == q) { pos = run[q]; run[q] = pos + 1; }
        g_perm_token[pos] = a >> 1;
        g_tok2row[a] = pos;
    }
}

// ------------------------------ launch --------------------------------------
extern "C" void kernel_launch(void* const* d_in, const int* in_sizes, int n_in,
                              void* d_out, int out_size) {
    const float* hs = (const float*)d_in[0];
    const float* wq = (const float*)d_in[2];
    const float* wk = (const float*)d_in[3];
    const float* wv = (const float*)d_in[4];
    const float* wo = (const float*)d_in[5];
    const float* n1 = (const float*)d_in[6];
    const float* n2 = (const float*)d_in[7];
    const float* n3 = (const float*)d_in[8];
    const float* n4 = (const float*)d_in[9];
    const float* router = (const float*)d_in[10];
    const float* we_w1 = (const float*)d_in[11];
    const float* we_v = (const float*)d_in[12];
    const float* we_d = (const float*)d_in[13];
    float* out = (float*)d_out;
    float* logits_out = (out_size >= S * H + S * E) ? out + (size_t)S * H : nullptr;

    cudaFuncSetAttribute(flashmma_kernel,
                         cudaFuncAttributeMaxDynamicSharedMemorySize, FSM_BYTES);
    cudaFuncSetAttribute(tgemm_qkv_kernel,
                         cudaFuncAttributeMaxDynamicSharedMemorySize, SMEM_TF);
    cudaFuncSetAttribute(tgemm_wo_kernel,
                         cudaFuncAttributeMaxDynamicSharedMemorySize, SMEM_TF);
    cudaFuncSetAttribute(bgemm_group_kernel,
                         cudaFuncAttributeMaxDynamicSharedMemorySize, SMEM_BF);

    // 1. attention input norm -> tf32 planes
    rmsnorm_attn_kernel<<<S, 256>>>(hs, n1);

    // 2. fused q/k/v projection (3xtf32, BK=32)
    tgemm_qkv_kernel<<<dim3(24, 8), 256, SMEM_TF>>>(wq, wk, wv);

    // 3. RoPE + split to planes; V split
    rope_split_kernel<<<(S * NH * 32 + 255) / 256, 256>>>(1, NH);
    rope_split_kernel<<<(S * NKV * 32 + 255) / 256, 256>>>(0, NKV);
    vsplit_kernel<<<(S * NKV * D + 255) / 256, 256>>>();

    // 4. tensor-core flash attention -> attn planes
    flashmma_kernel<<<dim3(8, NH), 256, FSM_BYTES>>>();

    // 5. output proj (3xtf32, BK=32) + residual rmsnorm -> g_hidden
    tgemm_wo_kernel<<<dim3(16, 8), 256, SMEM_TF>>>(wo);
    add_rmsnorm_kernel<<<S, 256>>>(hs, n2);

    // 6. MoE input norm -> fp32 (router) + bf16 split planes
    rmsnorm_moe_kernel<<<S, 256>>>(n3);

    // 7. routing + parallel plan
    router_kernel<<<S, 256>>>(router, logits_out);
    plan_kernel<<<1, 256>>>();

    // 8. expert GEMMs (bf16x2-split, LDSM A)
    bgemm_group_kernel<<<dim3(F / 128, 8, E), 256, SMEM_BF>>>(we_w1, 0);
    bgemm_group_kernel<<<dim3(F / 128, 8, E), 256, SMEM_BF>>>(we_v, 1);
    bgemm_group_kernel<<<dim3(H / 128, 8, E), 256, SMEM_BF>>>(we_d, 2);

    // 9. combine + final residual rmsnorm
    final_kernel<<<S, 256>>>(n4, out);
}